// round 5
// baseline (speedup 1.0000x reference)
#include <cuda_runtime.h>
#include <cstdint>

#define NTOK 49
#define DMODEL 128
#define NHEAD 4                       /* HEADS = DIM // DIM_HEAD = 128/32 = 4 */
#define DHEAD 32
#define N3 384
#define WINELEMS (NTOK * DMODEL)      /* 6272 */
#define XS_STRIDE 129
#define XS_SIZE 6322                  /* 49*129=6321, +1 pad to keep qkv base even */
#define QKV_STRIDE 386                /* even for float2 alignment */
#define QKV_SIZE (NTOK * QKV_STRIDE)  /* 18914 */
#define WT_SIZE (32 * N3)             /* 12288 floats: one 32-row k-chunk of W_qkv */
#define BIAS_SIZE 676                 /* 169*4 */
#define SMEM_FLOATS (XS_SIZE + QKV_SIZE + WT_SIZE + BIAS_SIZE)
#define SMEM_BYTES (SMEM_FLOATS * 4)  /* 152,800 B */
#define SCALE_Q 0.17677669529663687f  /* 32^-0.5 */

__device__ __forceinline__ void fma2f(float2& d, float2 a, float2 b) {
    d.x = fmaf(a.x, b.x, d.x);
    d.y = fmaf(a.y, b.y, d.y);
}

__global__ void __launch_bounds__(256, 1)
win_attn_kernel(const float* __restrict__ x,
                const float* __restrict__ Wqkv,
                const float* __restrict__ Wout,
                const float* __restrict__ btab,
                float* __restrict__ out)
{
    extern __shared__ float sm[];
    float* xs  = sm;                 // x tile, later attn_out [49][129]
    float* qkv = sm + XS_SIZE;       // [49][386] cols: q 0..127 | k 128..255 | v 256..383
    float* wt  = qkv + QKV_SIZE;     // weight staging [32][384] (or [32][128])
    float* bs  = wt + WT_SIZE;       // bias table [169][4]

    const int tid = threadIdx.x;
    const int tx = tid & 31, ty = tid >> 5;
    const size_t wbase = (size_t)blockIdx.x * WINELEMS;

    // ---------------- Phase 1: load bias table + x tile ----------------
    for (int i = tid; i < BIAS_SIZE; i += 256) bs[i] = btab[i];
    {
        const float4* xg = reinterpret_cast<const float4*>(x + wbase);
        #pragma unroll 1
        for (int i = tid; i < WINELEMS / 4; i += 256) {
            float4 v = xg[i];
            int r = i >> 5;             // 32 float4 per 128-wide row
            int c = (i & 31) << 2;
            float* p = xs + r * XS_STRIDE + c;
            p[0] = v.x; p[1] = v.y; p[2] = v.z; p[3] = v.w;
        }
    }

    // Per-thread row set for the two GEMM phases (rows ty, ty+8, ..., clamped)
    int rowv[7], xoff[7];
    #pragma unroll
    for (int rr = 0; rr < 7; ++rr) {
        int r = ty + 8 * rr;
        rowv[rr] = r;
        xoff[rr] = (r < NTOK ? r : NTOK - 1) * XS_STRIDE;
    }

    // ---------------- Phase 2: qkv[49][384] = xs @ Wqkv ----------------
    {
        float2 acc[7][6];
        #pragma unroll
        for (int rr = 0; rr < 7; ++rr)
            #pragma unroll
            for (int g = 0; g < 6; ++g) acc[rr][g] = make_float2(0.f, 0.f);

        #pragma unroll 1
        for (int kc = 0; kc < 4; ++kc) {
            __syncthreads();
            // stage 32 k-rows of W_qkv (once per CTA, shared by all 8 warps)
            {
                const float4* src = reinterpret_cast<const float4*>(Wqkv + kc * 32 * N3);
                float4* dst = reinterpret_cast<float4*>(wt);
                #pragma unroll 1
                for (int i = tid; i < WT_SIZE / 4; i += 256) dst[i] = src[i];
            }
            __syncthreads();
            const float2* wt2 = reinterpret_cast<const float2*>(wt);
            #pragma unroll 4
            for (int k = 0; k < 32; ++k) {
                float2 xv2[7];
                #pragma unroll
                for (int rr = 0; rr < 7; ++rr) {
                    float xv = xs[xoff[rr] + kc * 32 + k];   // smem broadcast
                    xv2[rr] = make_float2(xv, xv);
                }
                #pragma unroll
                for (int g = 0; g < 6; ++g) {
                    float2 w2 = wt2[k * 192 + g * 32 + tx];  // conflict-free LDS.64
                    #pragma unroll
                    for (int rr = 0; rr < 7; ++rr) fma2f(acc[rr][g], xv2[rr], w2);
                }
            }
        }
        #pragma unroll
        for (int rr = 0; rr < 7; ++rr) {
            if (rowv[rr] < NTOK) {
                float2* qrow = reinterpret_cast<float2*>(qkv + rowv[rr] * QKV_STRIDE);
                #pragma unroll
                for (int g = 0; g < 6; ++g) qrow[g * 32 + tx] = acc[rr][g];
            }
        }
    }
    __syncthreads();

    // ------- Phase 3: attention. 8 warps = 4 heads x 2 row-halves -------
    {
        const int h = ty & 3;           // head 0..3
        const int half = ty >> 2;       // row half: 0 -> rows 0..31, 1 -> rows 32..48
        const int i = half * 32 + tx;
        const bool act = (i < NTOK);
        const int ic = act ? i : NTOK - 1;

        // q row (scaled) into registers
        float2 q2[16];
        {
            const float2* qrow = reinterpret_cast<const float2*>(qkv + ic * QKV_STRIDE + h * DHEAD);
            #pragma unroll
            for (int d = 0; d < 16; ++d) {
                float2 t = qrow[d];
                q2[d] = make_float2(t.x * SCALE_Q, t.y * SCALE_Q);
            }
        }

        float simr[NTOK];
        int i7 = ic / 7, im = ic - i7 * 7;
        int ibase = i7 * 13 + im + 84;   // idx(j) = ibase - jb*13 - jj
        #pragma unroll 1
        for (int jb = 0; jb < 7; ++jb) {
            const float2* krow = reinterpret_cast<const float2*>(
                qkv + jb * 7 * QKV_STRIDE + DMODEL + h * DHEAD);
            int idxb = ibase - jb * 13;
            #pragma unroll
            for (int jj = 0; jj < 7; ++jj) {
                float2 a = make_float2(0.f, 0.f);
                const float2* kr = krow + jj * (QKV_STRIDE / 2);
                #pragma unroll
                for (int d = 0; d < 16; ++d) fma2f(a, q2[d], kr[d]);   // k broadcast
                simr[jb * 7 + jj] = a.x + a.y + bs[(idxb - jj) * NHEAD + h];
            }
        }

        // stable softmax
        float mx = simr[0];
        #pragma unroll 7
        for (int j = 1; j < NTOK; ++j) mx = fmaxf(mx, simr[j]);
        float ssum = 0.f;
        #pragma unroll 7
        for (int j = 0; j < NTOK; ++j) { float e = __expf(simr[j] - mx); simr[j] = e; ssum += e; }
        float inv = __frcp_rn(ssum);

        // out row = attn @ v
        float2 o2[16];
        #pragma unroll
        for (int d = 0; d < 16; ++d) o2[d] = make_float2(0.f, 0.f);
        #pragma unroll 1
        for (int jb = 0; jb < 7; ++jb) {
            const float2* vrow = reinterpret_cast<const float2*>(
                qkv + jb * 7 * QKV_STRIDE + 2 * DMODEL + h * DHEAD);
            #pragma unroll
            for (int jj = 0; jj < 7; ++jj) {
                float p = simr[jb * 7 + jj] * inv;
                float2 p2 = make_float2(p, p);
                const float2* vr = vrow + jj * (QKV_STRIDE / 2);
                #pragma unroll
                for (int d = 0; d < 16; ++d) fma2f(o2[d], p2, vr[d]);  // v broadcast
            }
        }
        if (act) {
            float* orow = xs + i * XS_STRIDE + h * DHEAD;  // attn_out overwrites x tile
            #pragma unroll
            for (int d = 0; d < 16; ++d) {
                orow[2 * d] = o2[d].x; orow[2 * d + 1] = o2[d].y;
            }
        }
    }
    __syncthreads();

    // ---------------- Phase 4: out = attn_out @ Wout ----------------
    {
        float2 acc[7][2];
        #pragma unroll
        for (int rr = 0; rr < 7; ++rr) {
            acc[rr][0] = make_float2(0.f, 0.f);
            acc[rr][1] = make_float2(0.f, 0.f);
        }

        #pragma unroll 1
        for (int kc = 0; kc < 4; ++kc) {
            __syncthreads();
            {
                const float4* src = reinterpret_cast<const float4*>(Wout + kc * 32 * DMODEL);
                float4* dst = reinterpret_cast<float4*>(wt);
                #pragma unroll 1
                for (int i = tid; i < (32 * DMODEL) / 4; i += 256) dst[i] = src[i];
            }
            __syncthreads();
            const float2* wt2 = reinterpret_cast<const float2*>(wt);
            #pragma unroll 4
            for (int k = 0; k < 32; ++k) {
                float2 xv2[7];
                #pragma unroll
                for (int rr = 0; rr < 7; ++rr) {
                    float xv = xs[xoff[rr] + kc * 32 + k];
                    xv2[rr] = make_float2(xv, xv);
                }
                #pragma unroll
                for (int g = 0; g < 2; ++g) {
                    float2 w2 = wt2[k * 64 + g * 32 + tx];
                    #pragma unroll
                    for (int rr = 0; rr < 7; ++rr) fma2f(acc[rr][g], xv2[rr], w2);
                }
            }
        }
        #pragma unroll
        for (int rr = 0; rr < 7; ++rr) {
            if (rowv[rr] < NTOK) {
                float2* orow = reinterpret_cast<float2*>(out + wbase + (size_t)rowv[rr] * DMODEL);
                #pragma unroll
                for (int g = 0; g < 2; ++g) orow[g * 32 + tx] = acc[rr][g];
            }
        }
    }
}

extern "C" void kernel_launch(void* const* d_in, const int* in_sizes, int n_in,
                              void* d_out, int out_size) {
    // Resolve inputs by element count; fall back to positional order if anything
    // fails to match (never launch with a null pointer).
    //   x = 8192*49*128 (largest), W_qkv = 49152, W_out = 16384, bias = 169*4 = 676
    const float* x = nullptr; const float* Wqkv = nullptr;
    const float* Wout = nullptr; const float* btab = nullptr;
    int xsize = 0;
    for (int i = 0; i < n_in; ++i) {
        int s = in_sizes[i];
        if (s == 3 * DMODEL * DMODEL)            Wqkv = (const float*)d_in[i];
        else if (s == DMODEL * DMODEL)           Wout = (const float*)d_in[i];
        else if (s == 169 * NHEAD)               btab = (const float*)d_in[i];
        else if (s > xsize) { x = (const float*)d_in[i]; xsize = s; }
    }
    if (!x || !Wqkv || !Wout || !btab || n_in < 4) {   // positional fallback
        x    = (const float*)d_in[0]; xsize = in_sizes[0];
        Wqkv = (const float*)d_in[1];
        Wout = (const float*)d_in[2];
        btab = (const float*)d_in[3];
    }
    float* out = (float*)d_out;
    (void)out_size;

    int nwin = xsize / WINELEMS;   // 8192 windows
    if (nwin <= 0) return;
    cudaFuncSetAttribute(win_attn_kernel,
                         cudaFuncAttributeMaxDynamicSharedMemorySize, SMEM_BYTES);
    win_attn_kernel<<<nwin, 256, SMEM_BYTES>>>(x, Wqkv, Wout, btab, out);
}

// round 7
// speedup vs baseline: 1.0957x; 1.0957x over previous
#include <cuda_runtime.h>
#include <cstdint>

#define NTOK 49
#define DMODEL 128
#define NHEAD 4                       /* HEADS = DIM // DIM_HEAD = 128/32 = 4 */
#define DHEAD 32
#define N3 384
#define WINELEMS (NTOK * DMODEL)      /* 6272 */
#define XS_STRIDE 129
#define XS_SIZE 6322                  /* 49*129=6321, +1 pad to keep qkv base even */
#define QKV_STRIDE 386                /* even for float2 alignment */
#define QKV_SIZE (NTOK * QKV_STRIDE)  /* 18914 */
#define WT_SIZE (32 * N3)             /* 12288 floats: one 32-row k-chunk of W_qkv */
#define BIAS_SIZE 676                 /* 169*4 */
#define SMEM_FLOATS (XS_SIZE + QKV_SIZE + WT_SIZE + BIAS_SIZE)
#define SMEM_BYTES (SMEM_FLOATS * 4)  /* 152,800 B */
#define SCALE_Q 0.17677669529663687f  /* 32^-0.5 */

typedef unsigned long long ull;

__device__ __forceinline__ ull pk2(float x, float y) {
    ull r; asm("mov.b64 %0, {%1, %2};" : "=l"(r) : "f"(x), "f"(y)); return r;
}
__device__ __forceinline__ float2 upk2(ull v) {
    float2 r; asm("mov.b64 {%0, %1}, %2;" : "=f"(r.x), "=f"(r.y) : "l"(v)); return r;
}
// d = a*b + d  (packed 2x fp32: full-rate Blackwell FMA path)
__device__ __forceinline__ void fma2(ull& d, ull a, ull b) {
    asm("fma.rn.f32x2 %0, %1, %2, %0;" : "+l"(d) : "l"(a), "l"(b));
}

__global__ void __launch_bounds__(256, 1)
win_attn_kernel(const float* __restrict__ x,
                const float* __restrict__ Wqkv,
                const float* __restrict__ Wout,
                const float* __restrict__ btab,
                float* __restrict__ out)
{
    extern __shared__ float sm[];
    float* xs  = sm;                 // x tile, later attn_out [49][129]
    float* qkv = sm + XS_SIZE;       // [49][386] cols: q 0..127 | k 128..255 | v 256..383
    float* wt  = qkv + QKV_SIZE;     // weight staging [32][384] (or [32][128])
    float* bs  = wt + WT_SIZE;       // bias table [169][4]

    const int tid = threadIdx.x;
    const int tx = tid & 31, ty = tid >> 5;
    const size_t wbase = (size_t)blockIdx.x * WINELEMS;

    // ---------------- Phase 1: load bias table + x tile ----------------
    for (int i = tid; i < BIAS_SIZE; i += 256) bs[i] = btab[i];
    {
        const float4* xg = reinterpret_cast<const float4*>(x + wbase);
        #pragma unroll 1
        for (int i = tid; i < WINELEMS / 4; i += 256) {
            float4 v = xg[i];
            int r = i >> 5;             // 32 float4 per 128-wide row
            int c = (i & 31) << 2;
            float* p = xs + r * XS_STRIDE + c;
            p[0] = v.x; p[1] = v.y; p[2] = v.z; p[3] = v.w;
        }
    }

    // Per-thread row set for the two GEMM phases (rows ty, ty+8, ..., clamped)
    int rowv[7], xoff[7];
    #pragma unroll
    for (int rr = 0; rr < 7; ++rr) {
        int r = ty + 8 * rr;
        rowv[rr] = r;
        xoff[rr] = (r < NTOK ? r : NTOK - 1) * XS_STRIDE;
    }

    // ---------------- Phase 2: qkv[49][384] = xs @ Wqkv ----------------
    {
        ull acc[7][6];
        #pragma unroll
        for (int rr = 0; rr < 7; ++rr)
            #pragma unroll
            for (int g = 0; g < 6; ++g) acc[rr][g] = 0ull;

        #pragma unroll 1
        for (int kc = 0; kc < 4; ++kc) {
            __syncthreads();
            // stage 32 k-rows of W_qkv (once per CTA, shared by all 8 warps)
            {
                const float4* src = reinterpret_cast<const float4*>(Wqkv + kc * 32 * N3);
                float4* dst = reinterpret_cast<float4*>(wt);
                #pragma unroll 1
                for (int i = tid; i < WT_SIZE / 4; i += 256) dst[i] = src[i];
            }
            __syncthreads();
            const ull* wt2 = reinterpret_cast<const ull*>(wt);
            #pragma unroll 4
            for (int k = 0; k < 32; ++k) {
                ull xv2[7];
                #pragma unroll
                for (int rr = 0; rr < 7; ++rr) {
                    float xv = xs[xoff[rr] + kc * 32 + k];   // smem broadcast
                    xv2[rr] = pk2(xv, xv);
                }
                #pragma unroll
                for (int g = 0; g < 6; ++g) {
                    ull w2 = wt2[k * 192 + g * 32 + tx];     // conflict-free LDS.64
                    #pragma unroll
                    for (int rr = 0; rr < 7; ++rr) fma2(acc[rr][g], xv2[rr], w2);
                }
            }
        }
        #pragma unroll
        for (int rr = 0; rr < 7; ++rr) {
            if (rowv[rr] < NTOK) {
                ull* qrow = reinterpret_cast<ull*>(qkv + rowv[rr] * QKV_STRIDE);
                #pragma unroll
                for (int g = 0; g < 6; ++g) qrow[g * 32 + tx] = acc[rr][g];
            }
        }
    }
    __syncthreads();

    // ------- Phase 3: attention. 8 warps = 4 heads x 2 row-halves -------
    {
        const int h = ty & 3;           // head 0..3
        const int half = ty >> 2;       // row half: 0 -> rows 0..31, 1 -> rows 32..48
        const int i = half * 32 + tx;
        const bool act = (i < NTOK);
        const int ic = act ? i : NTOK - 1;

        // q row (scaled) into registers
        ull q2[16];
        {
            const float2* qrow = reinterpret_cast<const float2*>(qkv + ic * QKV_STRIDE + h * DHEAD);
            #pragma unroll
            for (int d = 0; d < 16; ++d) {
                float2 t = qrow[d];
                q2[d] = pk2(t.x * SCALE_Q, t.y * SCALE_Q);
            }
        }

        float simr[NTOK];
        int i7 = ic / 7, im = ic - i7 * 7;
        int ibase = i7 * 13 + im + 84;   // idx(j) = ibase - jb*13 - jj
        #pragma unroll 1
        for (int jb = 0; jb < 7; ++jb) {
            const ull* krow = reinterpret_cast<const ull*>(
                qkv + jb * 7 * QKV_STRIDE + DMODEL + h * DHEAD);
            int idxb = ibase - jb * 13;
            #pragma unroll
            for (int jj = 0; jj < 7; ++jj) {
                const ull* kr = krow + jj * (QKV_STRIDE / 2);
                // 4 split accumulators: chain depth 16 -> 4
                ull a0 = 0ull, a1 = 0ull, a2 = 0ull, a3 = 0ull;
                #pragma unroll
                for (int d = 0; d < 4; ++d) {
                    fma2(a0, q2[4 * d + 0], kr[4 * d + 0]);
                    fma2(a1, q2[4 * d + 1], kr[4 * d + 1]);
                    fma2(a2, q2[4 * d + 2], kr[4 * d + 2]);
                    fma2(a3, q2[4 * d + 3], kr[4 * d + 3]);
                }
                float2 t0 = upk2(a0), t1 = upk2(a1), t2 = upk2(a2), t3 = upk2(a3);
                float s01 = (t0.x + t1.x) + (t0.y + t1.y);
                float s23 = (t2.x + t3.x) + (t2.y + t3.y);
                simr[jb * 7 + jj] = s01 + s23 + bs[(idxb - jj) * NHEAD + h];
            }
        }

        // stable softmax
        float mx = simr[0];
        #pragma unroll 7
        for (int j = 1; j < NTOK; ++j) mx = fmaxf(mx, simr[j]);
        float ssum = 0.f;
        #pragma unroll 7
        for (int j = 0; j < NTOK; ++j) { float e = __expf(simr[j] - mx); simr[j] = e; ssum += e; }
        float inv = __frcp_rn(ssum);

        // out row = attn @ v  (16 independent d-chains -> ILP is fine)
        ull o2[16];
        #pragma unroll
        for (int d = 0; d < 16; ++d) o2[d] = 0ull;
        #pragma unroll 1
        for (int jb = 0; jb < 7; ++jb) {
            const ull* vrow = reinterpret_cast<const ull*>(
                qkv + jb * 7 * QKV_STRIDE + 2 * DMODEL + h * DHEAD);
            #pragma unroll
            for (int jj = 0; jj < 7; ++jj) {
                float p = simr[jb * 7 + jj] * inv;
                ull p2 = pk2(p, p);
                const ull* vr = vrow + jj * (QKV_STRIDE / 2);
                #pragma unroll
                for (int d = 0; d < 16; ++d) fma2(o2[d], p2, vr[d]);  // v broadcast
            }
        }
        if (act) {
            float* orow = xs + i * XS_STRIDE + h * DHEAD;  // attn_out overwrites x tile
            #pragma unroll
            for (int d = 0; d < 16; ++d) {
                float2 t = upk2(o2[d]);
                orow[2 * d] = t.x; orow[2 * d + 1] = t.y;
            }
        }
    }
    __syncthreads();

    // ---------------- Phase 4: out = attn_out @ Wout ----------------
    {
        ull acc[7][2];
        #pragma unroll
        for (int rr = 0; rr < 7; ++rr) { acc[rr][0] = 0ull; acc[rr][1] = 0ull; }

        #pragma unroll 1
        for (int kc = 0; kc < 4; ++kc) {
            __syncthreads();
            {
                const float4* src = reinterpret_cast<const float4*>(Wout + kc * 32 * DMODEL);
                float4* dst = reinterpret_cast<float4*>(wt);
                #pragma unroll 1
                for (int i = tid; i < (32 * DMODEL) / 4; i += 256) dst[i] = src[i];
            }
            __syncthreads();
            const ull* wt2 = reinterpret_cast<const ull*>(wt);
            #pragma unroll 4
            for (int k = 0; k < 32; ++k) {
                ull xv2[7];
                #pragma unroll
                for (int rr = 0; rr < 7; ++rr) {
                    float xv = xs[xoff[rr] + kc * 32 + k];
                    xv2[rr] = pk2(xv, xv);
                }
                #pragma unroll
                for (int g = 0; g < 2; ++g) {
                    ull w2 = wt2[k * 64 + g * 32 + tx];
                    #pragma unroll
                    for (int rr = 0; rr < 7; ++rr) fma2(acc[rr][g], xv2[rr], w2);
                }
            }
        }
        #pragma unroll
        for (int rr = 0; rr < 7; ++rr) {
            if (rowv[rr] < NTOK) {
                float2* orow = reinterpret_cast<float2*>(out + wbase + (size_t)rowv[rr] * DMODEL);
                #pragma unroll
                for (int g = 0; g < 2; ++g) orow[g * 32 + tx] = upk2(acc[rr][g]);
            }
        }
    }
}

extern "C" void kernel_launch(void* const* d_in, const int* in_sizes, int n_in,
                              void* d_out, int out_size) {
    // Resolve inputs by element count; fall back to positional order if anything
    // fails to match (never launch with a null pointer).
    const float* x = nullptr; const float* Wqkv = nullptr;
    const float* Wout = nullptr; const float* btab = nullptr;
    int xsize = 0;
    for (int i = 0; i < n_in; ++i) {
        int s = in_sizes[i];
        if (s == 3 * DMODEL * DMODEL)            Wqkv = (const float*)d_in[i];
        else if (s == DMODEL * DMODEL)           Wout = (const float*)d_in[i];
        else if (s == 169 * NHEAD)               btab = (const float*)d_in[i];
        else if (s > xsize) { x = (const float*)d_in[i]; xsize = s; }
    }
    if (!x || !Wqkv || !Wout || !btab || n_in < 4) {   // positional fallback
        x    = (const float*)d_in[0]; xsize = in_sizes[0];
        Wqkv = (const float*)d_in[1];
        Wout = (const float*)d_in[2];
        btab = (const float*)d_in[3];
    }
    float* out = (float*)d_out;
    (void)out_size;

    int nwin = xsize / WINELEMS;   // 8192 windows
    if (nwin <= 0) return;
    cudaFuncSetAttribute(win_attn_kernel,
                         cudaFuncAttributeMaxDynamicSharedMemorySize, SMEM_BYTES);
    win_attn_kernel<<<nwin, 256, SMEM_BYTES>>>(x, Wqkv, Wout, btab, out);
}